// round 1
// baseline (speedup 1.0000x reference)
#include <cuda_runtime.h>
#include <cstddef>

#define NN 50000
#define EE 800000
#define FDIM 256
#define EPSBN 1e-5f

// ---------------- scratch (static device globals; no runtime allocation) ----
__device__ __align__(256) float g_h[(size_t)NN * FDIM];    // GEMM output
__device__ __align__(256) float g_out[(size_t)NN * FDIM];  // attention output
__device__ __align__(256) float g_act[(size_t)NN * FDIM];  // post BN+ReLU
__device__ __align__(256) float g_als[NN * 4];
__device__ __align__(256) float g_ald[NN * 4];
__device__ __align__(256) int   g_rowptr[2][NN + 1];
__device__ __align__(256) int   g_colidx[2][EE];
__device__ __align__(256) int   g_deg[NN];
__device__ __align__(256) int   g_cursor[NN];
__device__ __align__(256) int   g_bsums[64];
__device__ __align__(256) float g_bnstat[2 * FDIM];

// ---------------- small utility kernels ------------------------------------
__global__ void k_zero_deg() {
    int i = blockIdx.x * blockDim.x + threadIdx.x;
    if (i < NN) g_deg[i] = 0;
}
__global__ void k_zero_bn() {
    int i = blockIdx.x * blockDim.x + threadIdx.x;
    if (i < 2 * FDIM) g_bnstat[i] = 0.0f;
}

// ---------------- CSR build -------------------------------------------------
__global__ void k_hist(const int* __restrict__ ei) {
    int e = blockIdx.x * blockDim.x + threadIdx.x;
    if (e < EE) atomicAdd(&g_deg[ei[EE + e]], 1);
}

__global__ void k_scan1(int et) {
    __shared__ int sm[1024];
    int t = threadIdx.x;
    int idx = blockIdx.x * 1024 + t;
    int v = (idx < NN) ? g_deg[idx] : 0;
    sm[t] = v;
    __syncthreads();
    for (int off = 1; off < 1024; off <<= 1) {
        int u = (t >= off) ? sm[t - off] : 0;
        __syncthreads();
        sm[t] += u;
        __syncthreads();
    }
    if (idx < NN) g_rowptr[et][idx + 1] = sm[t];
    if (t == 1023) g_bsums[blockIdx.x] = sm[1023];
}

__global__ void k_scan2(int nb) {
    if (threadIdx.x == 0) {
        int run = 0;
        for (int i = 0; i < nb; i++) { int t = g_bsums[i]; g_bsums[i] = run; run += t; }
    }
}

__global__ void k_scan3(int et) {
    int idx = blockIdx.x * 1024 + threadIdx.x;
    if (idx < NN) g_rowptr[et][idx + 1] += g_bsums[blockIdx.x];
    if (idx == 0) g_rowptr[et][0] = 0;
}

__global__ void k_cursor(int et) {
    int i = blockIdx.x * blockDim.x + threadIdx.x;
    if (i < NN) g_cursor[i] = g_rowptr[et][i];
}

__global__ void k_scatter(const int* __restrict__ ei, int et) {
    int e = blockIdx.x * blockDim.x + threadIdx.x;
    if (e < EE) {
        int dst = ei[EE + e];
        int pos = atomicAdd(&g_cursor[dst], 1);
        g_colidx[et][pos] = ei[e];
    }
}

// ---------------- SGEMM: g_h = A(MxK) @ B(Kx256) ----------------------------
__global__ __launch_bounds__(256) void k_sgemm(const float* __restrict__ Aext, int useExt,
                                               const float* __restrict__ B, int M, int K) {
    const float* A = useExt ? Aext : g_act;
    __shared__ float As[8][128];
    __shared__ float Bs[8][128];
    int tid = threadIdx.x;
    int rowBase = blockIdx.x * 128;
    int colBase = blockIdx.y * 128;

    int aRow = tid >> 1;
    int aK = (tid & 1) * 4;
    int bK = tid >> 5;
    int bCol = (tid & 31) * 4;
    int rB = (tid >> 4) * 8;
    int cB = (tid & 15) * 8;

    float acc[8][8];
#pragma unroll
    for (int i = 0; i < 8; i++)
#pragma unroll
        for (int j = 0; j < 8; j++) acc[i][j] = 0.0f;

    for (int k0 = 0; k0 < K; k0 += 8) {
        float4 av = make_float4(0.f, 0.f, 0.f, 0.f);
        int gRow = rowBase + aRow;
        if (gRow < M) av = *(const float4*)(A + (size_t)gRow * K + k0 + aK);
        As[aK + 0][aRow] = av.x;
        As[aK + 1][aRow] = av.y;
        As[aK + 2][aRow] = av.z;
        As[aK + 3][aRow] = av.w;
        float4 bv = *(const float4*)(B + (size_t)(k0 + bK) * 256 + colBase + bCol);
        *(float4*)&Bs[bK][bCol] = bv;
        __syncthreads();
#pragma unroll
        for (int k = 0; k < 8; k++) {
            float a[8], b[8];
#pragma unroll
            for (int i = 0; i < 8; i++) a[i] = As[k][rB + i];
#pragma unroll
            for (int j = 0; j < 8; j++) b[j] = Bs[k][cB + j];
#pragma unroll
            for (int i = 0; i < 8; i++)
#pragma unroll
                for (int j = 0; j < 8; j++) acc[i][j] += a[i] * b[j];
        }
        __syncthreads();
    }

#pragma unroll
    for (int i = 0; i < 8; i++) {
        int r = rowBase + rB + i;
        if (r < M) {
            float4 o1 = make_float4(acc[i][0], acc[i][1], acc[i][2], acc[i][3]);
            float4 o2 = make_float4(acc[i][4], acc[i][5], acc[i][6], acc[i][7]);
            *(float4*)(g_h + (size_t)r * 256 + colBase + cB) = o1;
            *(float4*)(g_h + (size_t)r * 256 + colBase + cB + 4) = o2;
        }
    }
}

// ---------------- attention logits per node ---------------------------------
__global__ void k_al(const float* __restrict__ as_, const float* __restrict__ ad_) {
    int gt = blockIdx.x * blockDim.x + threadIdx.x;
    int w = gt >> 5, lane = gt & 31;
    if (w >= NN) return;
    const float4* hp = (const float4*)(g_h + (size_t)w * 256);
    float4 h1 = hp[lane * 2], h2 = hp[lane * 2 + 1];
    const float4* sp = (const float4*)as_;
    const float4* dp = (const float4*)ad_;
    float4 s1 = sp[lane * 2], s2 = sp[lane * 2 + 1];
    float4 d1 = dp[lane * 2], d2 = dp[lane * 2 + 1];
    float vs = h1.x * s1.x + h1.y * s1.y + h1.z * s1.z + h1.w * s1.w +
               h2.x * s2.x + h2.y * s2.y + h2.z * s2.z + h2.w * s2.w;
    float vd = h1.x * d1.x + h1.y * d1.y + h1.z * d1.z + h1.w * d1.w +
               h2.x * d2.x + h2.y * d2.y + h2.z * d2.z + h2.w * d2.w;
    vs += __shfl_down_sync(0xffffffffu, vs, 4, 8);
    vs += __shfl_down_sync(0xffffffffu, vs, 2, 8);
    vs += __shfl_down_sync(0xffffffffu, vs, 1, 8);
    vd += __shfl_down_sync(0xffffffffu, vd, 4, 8);
    vd += __shfl_down_sync(0xffffffffu, vd, 2, 8);
    vd += __shfl_down_sync(0xffffffffu, vd, 1, 8);
    if ((lane & 7) == 0) {
        g_als[w * 4 + (lane >> 3)] = vs;
        g_ald[w * 4 + (lane >> 3)] = vd;
    }
}

// ---------------- aggregation: one warp per destination node -----------------
__device__ __forceinline__ float lrelu02(float x) { return x > 0.f ? x : 0.2f * x; }

__global__ void k_agg(int et, const float* __restrict__ bias) {
    int gt = blockIdx.x * blockDim.x + threadIdx.x;
    int w = gt >> 5, lane = gt & 31;
    if (w >= NN) return;

    const float4 ald = *(const float4*)(g_ald + (size_t)w * 4);
    int start = g_rowptr[et][w];
    int end = g_rowptr[et][w + 1];
    int hsel = lane >> 4;  // 0 or 1

    float4 acc1 = make_float4(0, 0, 0, 0);
    float4 acc2 = make_float4(0, 0, 0, 0);
    float se0 = 0, se1 = 0, se2 = 0, se3 = 0;

#define PROCESS(SRC)                                                           \
    {                                                                          \
        int _s = (SRC);                                                        \
        float4 als = *(const float4*)(g_als + (size_t)_s * 4);                 \
        float x0 = __expf(lrelu02(als.x + ald.x));                             \
        float x1 = __expf(lrelu02(als.y + ald.y));                             \
        float x2 = __expf(lrelu02(als.z + ald.z));                             \
        float x3 = __expf(lrelu02(als.w + ald.w));                             \
        se0 += x0; se1 += x1; se2 += x2; se3 += x3;                            \
        float ex1 = hsel ? x1 : x0;                                            \
        float ex2 = hsel ? x3 : x2;                                            \
        const float4* hp = (const float4*)(g_h + (size_t)_s * 256);            \
        float4 v1 = hp[lane];                                                  \
        float4 v2 = hp[32 + lane];                                             \
        acc1.x += ex1 * v1.x; acc1.y += ex1 * v1.y;                            \
        acc1.z += ex1 * v1.z; acc1.w += ex1 * v1.w;                            \
        acc2.x += ex2 * v2.x; acc2.y += ex2 * v2.y;                            \
        acc2.z += ex2 * v2.z; acc2.w += ex2 * v2.w;                            \
    }

    PROCESS(w);  // self loop
    for (int e = start; e < end; e++) {
        int src = g_colidx[et][e];
        PROCESS(src);
    }
#undef PROCESS

    float inv1 = 1.0f / ((hsel ? se1 : se0) + 1e-16f);
    float inv2 = 1.0f / ((hsel ? se3 : se2) + 1e-16f);
    const float4* bp = (const float4*)bias;
    float4 b1 = bp[lane], b2 = bp[32 + lane];
    float4 o1 = make_float4(acc1.x * inv1 + b1.x, acc1.y * inv1 + b1.y,
                            acc1.z * inv1 + b1.z, acc1.w * inv1 + b1.w);
    float4 o2 = make_float4(acc2.x * inv2 + b2.x, acc2.y * inv2 + b2.y,
                            acc2.z * inv2 + b2.z, acc2.w * inv2 + b2.w);
    *(float4*)(g_out + (size_t)w * 256 + lane * 4) = o1;
    *(float4*)(g_out + (size_t)w * 256 + 128 + lane * 4) = o2;
}

// ---------------- batchnorm -------------------------------------------------
__global__ void k_bnstat() {
    int col = threadIdx.x;       // 256
    int b = blockIdx.x;          // 200
    int n0 = b * 250;
    float s = 0.f, s2 = 0.f;
    for (int n = n0; n < n0 + 250; n++) {
        float v = g_out[(size_t)n * 256 + col];
        s += v;
        s2 += v * v;
    }
    atomicAdd(&g_bnstat[col], s);
    atomicAdd(&g_bnstat[256 + col], s2);
}

__global__ void k_bnapply(const float* __restrict__ gam, const float* __restrict__ bet) {
    int i = blockIdx.x * blockDim.x + threadIdx.x;  // over NN*64 float4s
    if (i >= NN * 64) return;
    int colb = (i & 63) * 4;
    float4 v = ((const float4*)g_out)[i];
    float invN = 1.0f / (float)NN;
    float out[4];
    float vv[4] = {v.x, v.y, v.z, v.w};
#pragma unroll
    for (int c = 0; c < 4; c++) {
        float mu = g_bnstat[colb + c] * invN;
        float var = g_bnstat[256 + colb + c] * invN - mu * mu;
        float sc = gam[colb + c] * rsqrtf(var + EPSBN);
        float y = (vv[c] - mu) * sc + bet[colb + c];
        out[c] = y > 0.f ? y : 0.f;
    }
    ((float4*)g_act)[i] = make_float4(out[0], out[1], out[2], out[3]);
}

// ---------------- final linear 256 -> 32 ------------------------------------
__global__ void k_lin(const float* __restrict__ Wl, const float* __restrict__ bl,
                      float* __restrict__ out) {
    int gt = blockIdx.x * blockDim.x + threadIdx.x;
    int w = gt >> 5, lane = gt & 31;
    if (w >= NN) return;
    float acc = bl[lane];
    const float* arow = g_act + (size_t)w * 256;
    for (int kb = 0; kb < 256; kb += 32) {
        float av = arow[kb + lane];
#pragma unroll
        for (int kk = 0; kk < 32; kk++) {
            float a = __shfl_sync(0xffffffffu, av, kk);
            acc += a * Wl[(kb + kk) * 32 + lane];
        }
    }
    out[(size_t)w * 32 + lane] = acc;
}

// ---------------- launch ----------------------------------------------------
extern "C" void kernel_launch(void* const* d_in, const int* in_sizes, int n_in,
                              void* d_out, int out_size) {
    (void)in_sizes; (void)n_in; (void)out_size;
    const float* x = (const float*)d_in[0];
    const int* eis = (const int*)d_in[1];
    const int* eit = (const int*)d_in[2];
    const float* W[4]  = {(const float*)d_in[3],  (const float*)d_in[9],
                          (const float*)d_in[15], (const float*)d_in[21]};
    const float* AS[4] = {(const float*)d_in[4],  (const float*)d_in[10],
                          (const float*)d_in[16], (const float*)d_in[22]};
    const float* AD[4] = {(const float*)d_in[5],  (const float*)d_in[11],
                          (const float*)d_in[17], (const float*)d_in[23]};
    const float* BI[4] = {(const float*)d_in[6],  (const float*)d_in[12],
                          (const float*)d_in[18], (const float*)d_in[24]};
    const float* GA[4] = {(const float*)d_in[7],  (const float*)d_in[13],
                          (const float*)d_in[19], (const float*)d_in[25]};
    const float* BE[4] = {(const float*)d_in[8],  (const float*)d_in[14],
                          (const float*)d_in[20], (const float*)d_in[26]};
    const float* Wl = (const float*)d_in[27];
    const float* bl = (const float*)d_in[28];

    const int scanBlocks = (NN + 1023) / 1024;  // 49

    // Build both CSRs (dst-sorted)
    for (int et = 0; et < 2; et++) {
        const int* ei = et ? eit : eis;
        k_zero_deg<<<(NN + 255) / 256, 256>>>();
        k_hist<<<(EE + 255) / 256, 256>>>(ei);
        k_scan1<<<scanBlocks, 1024>>>(et);
        k_scan2<<<1, 32>>>(scanBlocks);
        k_scan3<<<scanBlocks, 1024>>>(et);
        k_cursor<<<(NN + 255) / 256, 256>>>(et);
        k_scatter<<<(EE + 255) / 256, 256>>>(ei, et);
    }

    int KK[4] = {128, 256, 256, 256};
    int ET[4] = {0, 0, 1, 1};
    dim3 ggemm((NN + 127) / 128, 2);

    for (int l = 0; l < 4; l++) {
        k_sgemm<<<ggemm, 256>>>(l == 0 ? x : nullptr, l == 0 ? 1 : 0, W[l], NN, KK[l]);
        k_al<<<(NN * 32 + 255) / 256, 256>>>(AS[l], AD[l]);
        k_agg<<<(NN * 32 + 255) / 256, 256>>>(ET[l], BI[l]);
        k_zero_bn<<<2, 256>>>();
        k_bnstat<<<200, 256>>>();
        k_bnapply<<<(NN * 64 + 255) / 256, 256>>>(GA[l], BE[l]);
    }
    k_lin<<<(NN * 32 + 255) / 256, 256>>>(Wl, bl, (float*)d_out);
}

// round 3
// speedup vs baseline: 1.2591x; 1.2591x over previous
#include <cuda_runtime.h>
#include <cuda_bf16.h>
#include <mma.h>
#include <cstdint>
#include <cstddef>

using namespace nvcuda;

#define NN 50000
#define NPAD 50048  // 391 * 128
#define EE 800000
#define EPSBN 1e-5f
#define NTILES 391

// ---------------- scratch (static device globals) ---------------------------
__device__ __align__(256) float g_h[(size_t)NPAD * 256];
__device__ __align__(256) float g_out[(size_t)NN * 256];
__device__ __align__(256) float g_act[(size_t)NPAD * 256];
__device__ __align__(256) float g_als[NN * 4];
__device__ __align__(256) float g_ald[NN * 4];
__device__ __align__(256) int   g_rowptr[2][NN + 1];
__device__ __align__(256) int   g_colidx[2][EE];
__device__ __align__(256) int   g_deg[NN];
__device__ __align__(256) int   g_cursor[NN];
__device__ __align__(256) int   g_bsums[64];
__device__ __align__(256) float g_bnstat[2 * 256];
__device__ __align__(256) __nv_bfloat16 g_wt_hi[4 * 256 * 256];  // [layer][n][k]
__device__ __align__(256) __nv_bfloat16 g_wt_lo[4 * 256 * 256];

__device__ __forceinline__ void split2(float a, float b, uint32_t& hi, uint32_t& lo) {
    __nv_bfloat162 h = __floats2bfloat162_rn(a, b);
    hi = *reinterpret_cast<uint32_t*>(&h);
    float ra = a - __bfloat162float(h.x);
    float rb = b - __bfloat162float(h.y);
    __nv_bfloat162 l = __floats2bfloat162_rn(ra, rb);
    lo = *reinterpret_cast<uint32_t*>(&l);
}

// ---------------- W preprocessing: fp32 [K,256] -> bf16 hi/lo [n][k] ---------
__global__ void k_wprep(const float* __restrict__ W1, const float* __restrict__ W2,
                        const float* __restrict__ W3, const float* __restrict__ W4) {
    int layer = blockIdx.y;
    const float* W = layer == 0 ? W1 : layer == 1 ? W2 : layer == 2 ? W3 : W4;
    int K = layer == 0 ? 128 : 256;
    int i = blockIdx.x * 256 + threadIdx.x;  // i = n*256 + k
    int n = i >> 8, k = i & 255;
    float v = (k < K) ? W[k * 256 + n] : 0.0f;
    __nv_bfloat16 h = __float2bfloat16_rn(v);
    float lo = v - __bfloat162float(h);
    g_wt_hi[layer * 65536 + i] = h;
    g_wt_lo[layer * 65536 + i] = __float2bfloat16_rn(lo);
}

// ---------------- WMMA bf16 split GEMM: g_h = A(MxK) @ W^T ------------------
// Block: 256 thr / 8 warps. Tile 128(M) x 128(N), BK=32. Warp tile 64x32.
typedef wmma::fragment<wmma::matrix_a, 16, 16, 16, __nv_bfloat16, wmma::row_major> FragA;
typedef wmma::fragment<wmma::matrix_b, 16, 16, 16, __nv_bfloat16, wmma::col_major> FragB;
typedef wmma::fragment<wmma::accumulator, 16, 16, 16, float> FragC;

#define SSTR 40  // smem row stride in bf16 (padding vs bank conflicts)

__global__ __launch_bounds__(256) void k_gemm_wmma(const float* __restrict__ Aext,
                                                   int useExt, int K, int layer) {
    __shared__ __nv_bfloat16 sAhi[128 * SSTR], sAlo[128 * SSTR];
    __shared__ __nv_bfloat16 sBhi[128 * SSTR], sBlo[128 * SSTR];
    const float* A = useExt ? Aext : g_act;
    const __nv_bfloat16* wbh = g_wt_hi + layer * 65536;
    const __nv_bfloat16* wbl = g_wt_lo + layer * 65536;
    int tid = threadIdx.x, wid = tid >> 5;
    int tbM = blockIdx.x * 128, tbN = blockIdx.y * 128;
    int wm = wid & 1, wn = wid >> 1;

    FragC acc[4][2];
#pragma unroll
    for (int i = 0; i < 4; i++)
#pragma unroll
        for (int j = 0; j < 2; j++) wmma::fill_fragment(acc[i][j], 0.0f);

    int nch = K >> 5;
    for (int c = 0; c < nch; c++) {
        int k0 = c * 32;
        // A: 128 rows x 32 k fp32 -> bf16 hi/lo
#pragma unroll
        for (int it = 0; it < 4; it++) {
            int u = it * 256 + tid;
            int m = u >> 3;
            int kq = (u & 7) * 4;
            int gr = tbM + m;
            float4 v = make_float4(0.f, 0.f, 0.f, 0.f);
            if (gr < NN) v = *(const float4*)(A + (size_t)gr * K + k0 + kq);
            uint32_t h01, l01, h23, l23;
            split2(v.x, v.y, h01, l01);
            split2(v.z, v.w, h23, l23);
            *(uint2*)&sAhi[m * SSTR + kq] = make_uint2(h01, h23);
            *(uint2*)&sAlo[m * SSTR + kq] = make_uint2(l01, l23);
        }
        // B: 128 n-rows x 32 k bf16 (pre-split)
#pragma unroll
        for (int it = 0; it < 2; it++) {
            int u = it * 256 + tid;
            int n = u >> 2;
            int kq = (u & 3) * 8;
            *(uint4*)&sBhi[n * SSTR + kq] = *(const uint4*)(wbh + (size_t)(tbN + n) * 256 + k0 + kq);
            *(uint4*)&sBlo[n * SSTR + kq] = *(const uint4*)(wbl + (size_t)(tbN + n) * 256 + k0 + kq);
        }
        __syncthreads();

#pragma unroll
        for (int ks = 0; ks < 32; ks += 16) {
            FragA ahi[4], alo[4];
            FragB bhi[2], blo[2];
#pragma unroll
            for (int i = 0; i < 4; i++) {
                wmma::load_matrix_sync(ahi[i], &sAhi[(wm * 64 + i * 16) * SSTR + ks], SSTR);
                wmma::load_matrix_sync(alo[i], &sAlo[(wm * 64 + i * 16) * SSTR + ks], SSTR);
            }
#pragma unroll
            for (int j = 0; j < 2; j++) {
                wmma::load_matrix_sync(bhi[j], &sBhi[(wn * 32 + j * 16) * SSTR + ks], SSTR);
                wmma::load_matrix_sync(blo[j], &sBlo[(wn * 32 + j * 16) * SSTR + ks], SSTR);
            }
#pragma unroll
            for (int i = 0; i < 4; i++)
#pragma unroll
                for (int j = 0; j < 2; j++) {
                    wmma::mma_sync(acc[i][j], ahi[i], bhi[j], acc[i][j]);
                    wmma::mma_sync(acc[i][j], ahi[i], blo[j], acc[i][j]);
                    wmma::mma_sync(acc[i][j], alo[i], bhi[j], acc[i][j]);
                }
        }
        __syncthreads();
    }

#pragma unroll
    for (int i = 0; i < 4; i++)
#pragma unroll
        for (int j = 0; j < 2; j++)
            wmma::store_matrix_sync(
                g_h + (size_t)(tbM + wm * 64 + i * 16) * 256 + tbN + wn * 32 + j * 16,
                acc[i][j], 256, wmma::mem_row_major);
}

// ---------------- attention logits per node ---------------------------------
__global__ void k_al(const float* __restrict__ as_, const float* __restrict__ ad_) {
    int gt = blockIdx.x * blockDim.x + threadIdx.x;
    int w = gt >> 5, lane = gt & 31;
    if (w >= NN) return;
    const float4* hp = (const float4*)(g_h + (size_t)w * 256);
    float4 h1 = hp[lane * 2], h2 = hp[lane * 2 + 1];
    const float4* sp = (const float4*)as_;
    const float4* dp = (const float4*)ad_;
    float4 s1 = sp[lane * 2], s2 = sp[lane * 2 + 1];
    float4 d1 = dp[lane * 2], d2 = dp[lane * 2 + 1];
    float vs = h1.x * s1.x + h1.y * s1.y + h1.z * s1.z + h1.w * s1.w +
               h2.x * s2.x + h2.y * s2.y + h2.z * s2.z + h2.w * s2.w;
    float vd = h1.x * d1.x + h1.y * d1.y + h1.z * d1.z + h1.w * d1.w +
               h2.x * d2.x + h2.y * d2.y + h2.z * d2.z + h2.w * d2.w;
    vs += __shfl_down_sync(0xffffffffu, vs, 4, 8);
    vs += __shfl_down_sync(0xffffffffu, vs, 2, 8);
    vs += __shfl_down_sync(0xffffffffu, vs, 1, 8);
    vd += __shfl_down_sync(0xffffffffu, vd, 4, 8);
    vd += __shfl_down_sync(0xffffffffu, vd, 2, 8);
    vd += __shfl_down_sync(0xffffffffu, vd, 1, 8);
    if ((lane & 7) == 0) {
        g_als[w * 4 + (lane >> 3)] = vs;
        g_ald[w * 4 + (lane >> 3)] = vd;
    }
}

// ---------------- small utility kernels --------------------------------------
__global__ void k_zero_deg() {
    int i = blockIdx.x * blockDim.x + threadIdx.x;
    if (i < NN) g_deg[i] = 0;
}
__global__ void k_zero_bn() {
    int i = blockIdx.x * blockDim.x + threadIdx.x;
    if (i < 2 * 256) g_bnstat[i] = 0.0f;
}

// ---------------- CSR build ---------------------------------------------------
__global__ void k_hist(const int* __restrict__ ei) {
    int e = blockIdx.x * blockDim.x + threadIdx.x;
    if (e < EE) atomicAdd(&g_deg[ei[EE + e]], 1);
}
__global__ void k_scan1(int et) {
    __shared__ int sm[1024];
    int t = threadIdx.x;
    int idx = blockIdx.x * 1024 + t;
    int v = (idx < NN) ? g_deg[idx] : 0;
    sm[t] = v;
    __syncthreads();
    for (int off = 1; off < 1024; off <<= 1) {
        int u = (t >= off) ? sm[t - off] : 0;
        __syncthreads();
        sm[t] += u;
        __syncthreads();
    }
    if (idx < NN) g_rowptr[et][idx + 1] = sm[t];
    if (t == 1023) g_bsums[blockIdx.x] = sm[1023];
}
__global__ void k_scan2(int nb) {
    if (threadIdx.x == 0) {
        int run = 0;
        for (int i = 0; i < nb; i++) { int t = g_bsums[i]; g_bsums[i] = run; run += t; }
    }
}
__global__ void k_scan3(int et) {
    int idx = blockIdx.x * 1024 + threadIdx.x;
    if (idx < NN) g_rowptr[et][idx + 1] += g_bsums[blockIdx.x];
    if (idx == 0) g_rowptr[et][0] = 0;
}
__global__ void k_cursor(int et) {
    int i = blockIdx.x * blockDim.x + threadIdx.x;
    if (i < NN) g_cursor[i] = g_rowptr[et][i];
}
__global__ void k_scatter(const int* __restrict__ ei, int et) {
    int e = blockIdx.x * blockDim.x + threadIdx.x;
    if (e < EE) {
        int dst = ei[EE + e];
        int pos = atomicAdd(&g_cursor[dst], 1);
        g_colidx[et][pos] = ei[e];
    }
}

// ---------------- aggregation: one warp per destination node ------------------
__device__ __forceinline__ float lrelu02(float x) { return x > 0.f ? x : 0.2f * x; }

__global__ void k_agg(int et, const float* __restrict__ bias) {
    int gt = blockIdx.x * blockDim.x + threadIdx.x;
    int w = gt >> 5, lane = gt & 31;
    if (w >= NN) return;

    const float4 ald = *(const float4*)(g_ald + (size_t)w * 4);
    int start = g_rowptr[et][w];
    int end = g_rowptr[et][w + 1];
    int hsel = lane >> 4;

    float4 acc1 = make_float4(0, 0, 0, 0);
    float4 acc2 = make_float4(0, 0, 0, 0);
    float se0 = 0, se1 = 0, se2 = 0, se3 = 0;

#define PROCESS(SRC)                                                           \
    {                                                                          \
        int _s = (SRC);                                                        \
        float4 als = *(const float4*)(g_als + (size_t)_s * 4);                 \
        float x0 = __expf(lrelu02(als.x + ald.x));                             \
        float x1 = __expf(lrelu02(als.y + ald.y));                             \
        float x2 = __expf(lrelu02(als.z + ald.z));                             \
        float x3 = __expf(lrelu02(als.w + ald.w));                             \
        se0 += x0; se1 += x1; se2 += x2; se3 += x3;                            \
        float ex1 = hsel ? x1 : x0;                                            \
        float ex2 = hsel ? x3 : x2;                                            \
        const float4* hp = (const float4*)(g_h + (size_t)_s * 256);            \
        float4 v1 = hp[lane];                                                  \
        float4 v2 = hp[32 + lane];                                             \
        acc1.x += ex1 * v1.x; acc1.y += ex1 * v1.y;                            \
        acc1.z += ex1 * v1.z; acc1.w += ex1 * v1.w;                            \
        acc2.x += ex2 * v2.x; acc2.y += ex2 * v2.y;                            \
        acc2.z += ex2 * v2.z; acc2.w += ex2 * v2.w;                            \
    }

    PROCESS(w);
    for (int e = start; e < end; e++) {
        int src = g_colidx[et][e];
        PROCESS(src);
    }
#undef PROCESS

    float inv1 = 1.0f / ((hsel ? se1 : se0) + 1e-16f);
    float inv2 = 1.0f / ((hsel ? se3 : se2) + 1e-16f);
    const float4* bp = (const float4*)bias;
    float4 b1 = bp[lane], b2 = bp[32 + lane];
    float4 o1 = make_float4(acc1.x * inv1 + b1.x, acc1.y * inv1 + b1.y,
                            acc1.z * inv1 + b1.z, acc1.w * inv1 + b1.w);
    float4 o2 = make_float4(acc2.x * inv2 + b2.x, acc2.y * inv2 + b2.y,
                            acc2.z * inv2 + b2.z, acc2.w * inv2 + b2.w);
    *(float4*)(g_out + (size_t)w * 256 + lane * 4) = o1;
    *(float4*)(g_out + (size_t)w * 256 + 128 + lane * 4) = o2;
}

// ---------------- batchnorm ---------------------------------------------------
__global__ void k_bnstat() {
    int col = threadIdx.x;
    int b = blockIdx.x;
    int n0 = b * 250;
    float s = 0.f, s2 = 0.f;
    for (int n = n0; n < n0 + 250; n++) {
        float v = g_out[(size_t)n * 256 + col];
        s += v;
        s2 += v * v;
    }
    atomicAdd(&g_bnstat[col], s);
    atomicAdd(&g_bnstat[256 + col], s2);
}

__global__ void k_bnapply(const float* __restrict__ gam, const float* __restrict__ bet) {
    int i = blockIdx.x * blockDim.x + threadIdx.x;
    if (i >= NN * 64) return;
    int colb = (i & 63) * 4;
    float4 v = ((const float4*)g_out)[i];
    float invN = 1.0f / (float)NN;
    float out[4];
    float vv[4] = {v.x, v.y, v.z, v.w};
#pragma unroll
    for (int c = 0; c < 4; c++) {
        float mu = g_bnstat[colb + c] * invN;
        float var = g_bnstat[256 + colb + c] * invN - mu * mu;
        float sc = gam[colb + c] * rsqrtf(var + EPSBN);
        float y = (vv[c] - mu) * sc + bet[colb + c];
        out[c] = y > 0.f ? y : 0.f;
    }
    ((float4*)g_act)[i] = make_float4(out[0], out[1], out[2], out[3]);
}

// ---------------- final linear 256 -> 32 --------------------------------------
__global__ void k_lin(const float* __restrict__ Wl, const float* __restrict__ bl,
                      float* __restrict__ out) {
    int gt = blockIdx.x * blockDim.x + threadIdx.x;
    int w = gt >> 5, lane = gt & 31;
    if (w >= NN) return;
    float acc = bl[lane];
    const float* arow = g_act + (size_t)w * 256;
    for (int kb = 0; kb < 256; kb += 32) {
        float av = arow[kb + lane];
#pragma unroll
        for (int kk = 0; kk < 32; kk++) {
            float a = __shfl_sync(0xffffffffu, av, kk);
            acc += a * Wl[(kb + kk) * 32 + lane];
        }
    }
    out[(size_t)w * 32 + lane] = acc;
}

// ---------------- launch ------------------------------------------------------
extern "C" void kernel_launch(void* const* d_in, const int* in_sizes, int n_in,
                              void* d_out, int out_size) {
    (void)in_sizes; (void)n_in; (void)out_size;
    const float* x = (const float*)d_in[0];
    const int* eis = (const int*)d_in[1];
    const int* eit = (const int*)d_in[2];
    const float* W[4]  = {(const float*)d_in[3],  (const float*)d_in[9],
                          (const float*)d_in[15], (const float*)d_in[21]};
    const float* AS[4] = {(const float*)d_in[4],  (const float*)d_in[10],
                          (const float*)d_in[16], (const float*)d_in[22]};
    const float* AD[4] = {(const float*)d_in[5],  (const float*)d_in[11],
                          (const float*)d_in[17], (const float*)d_in[23]};
    const float* BI[4] = {(const float*)d_in[6],  (const float*)d_in[12],
                          (const float*)d_in[18], (const float*)d_in[24]};
    const float* GA[4] = {(const float*)d_in[7],  (const float*)d_in[13],
                          (const float*)d_in[19], (const float*)d_in[25]};
    const float* BE[4] = {(const float*)d_in[8],  (const float*)d_in[14],
                          (const float*)d_in[20], (const float*)d_in[26]};
    const float* Wl = (const float*)d_in[27];
    const float* bl = (const float*)d_in[28];

    const int scanBlocks = (NN + 1023) / 1024;
    dim3 ggemm(NTILES, 2);

    k_wprep<<<dim3(256, 4), 256>>>(W[0], W[1], W[2], W[3]);

    // CSR build for both edge types; layer-1 GEMM interleaved
    k_zero_deg<<<(NN + 255) / 256, 256>>>();
    k_hist<<<(EE + 255) / 256, 256>>>(eis);
    k_gemm_wmma<<<ggemm, 256>>>(x, 1, 128, 0);
    k_scan1<<<scanBlocks, 1024>>>(0);
    k_scan2<<<1, 32>>>(scanBlocks);
    k_scan3<<<scanBlocks, 1024>>>(0);
    k_cursor<<<(NN + 255) / 256, 256>>>(0);
    k_scatter<<<(EE + 255) / 256, 256>>>(eis, 0);

    k_zero_deg<<<(NN + 255) / 256, 256>>>();
    k_hist<<<(EE + 255) / 256, 256>>>(eit);
    k_scan1<<<scanBlocks, 1024>>>(1);
    k_scan2<<<1, 32>>>(scanBlocks);
    k_scan3<<<scanBlocks, 1024>>>(1);
    k_cursor<<<(NN + 255) / 256, 256>>>(1);
    k_scatter<<<(EE + 255) / 256, 256>>>(eit, 1);

    int ET[4] = {0, 0, 1, 1};
    for (int l = 0; l < 4; l++) {
        if (l > 0) k_gemm_wmma<<<ggemm, 256>>>(nullptr, 0, 256, l);
        k_al<<<(NN * 32 + 255) / 256, 256>>>(AS[l], AD[l]);
        k_agg<<<(NN * 32 + 255) / 256, 256>>>(ET[l], BI[l]);
        k_zero_bn<<<2, 256>>>();
        k_bnstat<<<200, 256>>>();
        k_bnapply<<<(NN * 64 + 255) / 256, 256>>>(GA[l], BE[l]);
    }
    k_lin<<<(NN * 32 + 255) / 256, 256>>>(Wl, bl, (float*)d_out);
}

// round 4
// speedup vs baseline: 1.3266x; 1.0535x over previous
#include <cuda_runtime.h>
#include <cuda_bf16.h>
#include <mma.h>
#include <cstdint>
#include <cstddef>

using namespace nvcuda;

#define NN 50000
#define NPAD 50048  // 391 * 128
#define EE 800000
#define EPSBN 1e-5f
#define NTILES 391

// ---------------- scratch (static device globals) ---------------------------
__device__ __align__(256) float g_h[(size_t)NPAD * 256];
__device__ __align__(256) float g_out[(size_t)NN * 256];
__device__ __align__(256) float g_als[NN * 4];
__device__ __align__(256) float g_ald[NN * 4];
__device__ __align__(256) int   g_rowptr[2][NN + 1];
__device__ __align__(256) int   g_colidx[2][EE];
__device__ __align__(256) int   g_deg[NN];
__device__ __align__(256) int   g_cursor[NN];
__device__ __align__(256) int   g_bsums[64];
__device__ __align__(256) float g_bnstat[2 * 256];
__device__ __align__(256) __nv_bfloat16 g_wt_hi[4 * 256 * 256];  // [layer][n][k]
__device__ __align__(256) __nv_bfloat16 g_wt_lo[4 * 256 * 256];
__device__ __align__(256) __nv_bfloat16 g_a_hi[(size_t)NPAD * 256];  // A operand hi
__device__ __align__(256) __nv_bfloat16 g_a_lo[(size_t)NPAD * 256];  // A operand lo

__device__ __forceinline__ void split2(float a, float b, uint32_t& hi, uint32_t& lo) {
    __nv_bfloat162 h = __floats2bfloat162_rn(a, b);
    hi = *reinterpret_cast<uint32_t*>(&h);
    float ra = a - __bfloat162float(h.x);
    float rb = b - __bfloat162float(h.y);
    __nv_bfloat162 l = __floats2bfloat162_rn(ra, rb);
    lo = *reinterpret_cast<uint32_t*>(&l);
}

__device__ __forceinline__ uint32_t smem_u32(const void* p) {
    uint32_t a;
    asm("{ .reg .u64 t; cvta.to.shared.u64 t, %1; cvt.u32.u64 %0, t; }" : "=r"(a) : "l"(p));
    return a;
}
__device__ __forceinline__ void cp16(uint32_t s, const void* g) {
    asm volatile("cp.async.cg.shared.global [%0], [%1], 16;" :: "r"(s), "l"(g));
}
#define CP_COMMIT asm volatile("cp.async.commit_group;")

// ---------------- W preprocessing: fp32 [K,256] -> bf16 hi/lo [n][k] ---------
__global__ void k_wprep(const float* __restrict__ W1, const float* __restrict__ W2,
                        const float* __restrict__ W3, const float* __restrict__ W4) {
    int layer = blockIdx.y;
    const float* W = layer == 0 ? W1 : layer == 1 ? W2 : layer == 2 ? W3 : W4;
    int K = layer == 0 ? 128 : 256;
    int i = blockIdx.x * 256 + threadIdx.x;  // i = n*256 + k
    int n = i >> 8, k = i & 255;
    float v = (k < K) ? W[k * 256 + n] : 0.0f;
    __nv_bfloat16 h = __float2bfloat16_rn(v);
    float lo = v - __bfloat162float(h);
    g_wt_hi[layer * 65536 + i] = h;
    g_wt_lo[layer * 65536 + i] = __float2bfloat16_rn(lo);
}

// ---------------- x preprocessing: fp32 [N,128] -> bf16 hi/lo ---------------
__global__ void k_xprep(const float* __restrict__ x) {
    int i = blockIdx.x * 256 + threadIdx.x;  // over NN*32 float4s
    if (i >= NN * 32) return;
    float4 v = ((const float4*)x)[i];
    uint32_t h01, l01, h23, l23;
    split2(v.x, v.y, h01, l01);
    split2(v.z, v.w, h23, l23);
    *(uint2*)(g_a_hi + (size_t)i * 4) = make_uint2(h01, h23);
    *(uint2*)(g_a_lo + (size_t)i * 4) = make_uint2(l01, l23);
}

// ---------------- WMMA bf16 split GEMM: g_h = A(MxK) @ W^T ------------------
typedef wmma::fragment<wmma::matrix_a, 16, 16, 16, __nv_bfloat16, wmma::row_major> FragA;
typedef wmma::fragment<wmma::matrix_b, 16, 16, 16, __nv_bfloat16, wmma::col_major> FragB;
typedef wmma::fragment<wmma::accumulator, 16, 16, 16, float> FragC;

#define SSTR 40
#define PSTG 5120          // elems per (stage,part) plane: 128*SSTR
#define SMEM_GEMM (2 * 2 * PSTG * 2 * 2 * 2)  // bytes = 81920

__global__ __launch_bounds__(256) void k_gemm2(int K, int layer) {
    extern __shared__ __nv_bfloat16 sm[];
    const __nv_bfloat16* gAh = g_a_hi;
    const __nv_bfloat16* gAl = g_a_lo;
    const __nv_bfloat16* gBh = g_wt_hi + layer * 65536;
    const __nv_bfloat16* gBl = g_wt_lo + layer * 65536;
    int tid = threadIdx.x, wid = tid >> 5;
    int tbM = blockIdx.x * 128, tbN = blockIdx.y * 128;
    int wm = wid & 1, wn = wid >> 1;
    uint32_t sbase = smem_u32(sm);

    FragC acc[4][2];
#pragma unroll
    for (int i = 0; i < 4; i++)
#pragma unroll
        for (int j = 0; j < 2; j++) wmma::fill_fragment(acc[i][j], 0.0f);

    int nch = K >> 5;

#define PREFETCH(stage, k0)                                                        \
    {                                                                              \
        _Pragma("unroll")                                                          \
        for (int r = 0; r < 2; r++) {                                              \
            int q = r * 256 + tid;                                                 \
            int row = q >> 2;                                                      \
            int cq = (q & 3) * 8;                                                  \
            size_t ga = (size_t)(tbM + row) * K + (k0) + cq;                       \
            size_t gb = (size_t)(tbN + row) * 256 + (k0) + cq;                     \
            uint32_t so = (uint32_t)(((stage) * 2) * PSTG + row * SSTR + cq) * 2;  \
            cp16(sbase + so, gAh + ga);                                            \
            cp16(sbase + so + PSTG * 2, gAl + ga);                                 \
            cp16(sbase + so + 4 * PSTG * 2, gBh + gb);                             \
            cp16(sbase + so + 5 * PSTG * 2, gBl + gb);                             \
        }                                                                          \
    }

    PREFETCH(0, 0);
    CP_COMMIT;
    for (int c = 0; c < nch; c++) {
        if (c + 1 < nch) {
            PREFETCH((c + 1) & 1, (c + 1) * 32);
            CP_COMMIT;
            asm volatile("cp.async.wait_group 1;");
        } else {
            asm volatile("cp.async.wait_group 0;");
        }
        __syncthreads();
        int st = c & 1;
        const __nv_bfloat16* pAh = sm + (st * 2 + 0) * PSTG;
        const __nv_bfloat16* pAl = sm + (st * 2 + 1) * PSTG;
        const __nv_bfloat16* pBh = sm + 4 * PSTG + (st * 2 + 0) * PSTG;
        const __nv_bfloat16* pBl = sm + 4 * PSTG + (st * 2 + 1) * PSTG;
#pragma unroll
        for (int ks = 0; ks < 32; ks += 16) {
            FragB bhi[2], blo[2];
#pragma unroll
            for (int j = 0; j < 2; j++) {
                wmma::load_matrix_sync(bhi[j], &pBh[(wn * 32 + j * 16) * SSTR + ks], SSTR);
                wmma::load_matrix_sync(blo[j], &pBl[(wn * 32 + j * 16) * SSTR + ks], SSTR);
            }
#pragma unroll
            for (int i = 0; i < 4; i++) {
                FragA ah, al;
                wmma::load_matrix_sync(ah, &pAh[(wm * 64 + i * 16) * SSTR + ks], SSTR);
                wmma::load_matrix_sync(al, &pAl[(wm * 64 + i * 16) * SSTR + ks], SSTR);
#pragma unroll
                for (int j = 0; j < 2; j++) {
                    wmma::mma_sync(acc[i][j], ah, bhi[j], acc[i][j]);
                    wmma::mma_sync(acc[i][j], ah, blo[j], acc[i][j]);
                    wmma::mma_sync(acc[i][j], al, bhi[j], acc[i][j]);
                }
            }
        }
        __syncthreads();
    }

#pragma unroll
    for (int i = 0; i < 4; i++)
#pragma unroll
        for (int j = 0; j < 2; j++)
            wmma::store_matrix_sync(
                g_h + (size_t)(tbM + wm * 64 + i * 16) * 256 + tbN + wn * 32 + j * 16,
                acc[i][j], 256, wmma::mem_row_major);
}

// ---------------- attention logits per node ---------------------------------
__global__ void k_al(const float* __restrict__ as_, const float* __restrict__ ad_) {
    int gt = blockIdx.x * blockDim.x + threadIdx.x;
    int w = gt >> 5, lane = gt & 31;
    if (w >= NN) return;
    const float4* hp = (const float4*)(g_h + (size_t)w * 256);
    float4 h1 = hp[lane * 2], h2 = hp[lane * 2 + 1];
    const float4* sp = (const float4*)as_;
    const float4* dp = (const float4*)ad_;
    float4 s1 = sp[lane * 2], s2 = sp[lane * 2 + 1];
    float4 d1 = dp[lane * 2], d2 = dp[lane * 2 + 1];
    float vs = h1.x * s1.x + h1.y * s1.y + h1.z * s1.z + h1.w * s1.w +
               h2.x * s2.x + h2.y * s2.y + h2.z * s2.z + h2.w * s2.w;
    float vd = h1.x * d1.x + h1.y * d1.y + h1.z * d1.z + h1.w * d1.w +
               h2.x * d2.x + h2.y * d2.y + h2.z * d2.z + h2.w * d2.w;
    vs += __shfl_down_sync(0xffffffffu, vs, 4, 8);
    vs += __shfl_down_sync(0xffffffffu, vs, 2, 8);
    vs += __shfl_down_sync(0xffffffffu, vs, 1, 8);
    vd += __shfl_down_sync(0xffffffffu, vd, 4, 8);
    vd += __shfl_down_sync(0xffffffffu, vd, 2, 8);
    vd += __shfl_down_sync(0xffffffffu, vd, 1, 8);
    if ((lane & 7) == 0) {
        g_als[w * 4 + (lane >> 3)] = vs;
        g_ald[w * 4 + (lane >> 3)] = vd;
    }
}

// ---------------- small utility kernels --------------------------------------
__global__ void k_zero_deg() {
    int i = blockIdx.x * blockDim.x + threadIdx.x;
    if (i < NN) g_deg[i] = 0;
}
__global__ void k_zero_bn() {
    int i = blockIdx.x * blockDim.x + threadIdx.x;
    if (i < 2 * 256) g_bnstat[i] = 0.0f;
}

// ---------------- CSR build ---------------------------------------------------
__global__ void k_hist(const int* __restrict__ ei) {
    int e = blockIdx.x * blockDim.x + threadIdx.x;
    if (e < EE) atomicAdd(&g_deg[ei[EE + e]], 1);
}
__global__ void k_scan1(int et) {
    __shared__ int sm[1024];
    int t = threadIdx.x;
    int idx = blockIdx.x * 1024 + t;
    int v = (idx < NN) ? g_deg[idx] : 0;
    sm[t] = v;
    __syncthreads();
    for (int off = 1; off < 1024; off <<= 1) {
        int u = (t >= off) ? sm[t - off] : 0;
        __syncthreads();
        sm[t] += u;
        __syncthreads();
    }
    if (idx < NN) g_rowptr[et][idx + 1] = sm[t];
    if (t == 1023) g_bsums[blockIdx.x] = sm[1023];
}
__global__ void k_scan2(int nb) {
    if (threadIdx.x == 0) {
        int run = 0;
        for (int i = 0; i < nb; i++) { int t = g_bsums[i]; g_bsums[i] = run; run += t; }
    }
}
__global__ void k_scan3(int et) {
    int idx = blockIdx.x * 1024 + threadIdx.x;
    if (idx < NN) g_rowptr[et][idx + 1] += g_bsums[blockIdx.x];
    if (idx == 0) g_rowptr[et][0] = 0;
}
__global__ void k_cursor(int et) {
    int i = blockIdx.x * blockDim.x + threadIdx.x;
    if (i < NN) g_cursor[i] = g_rowptr[et][i];
}
__global__ void k_scatter(const int* __restrict__ ei, int et) {
    int e = blockIdx.x * blockDim.x + threadIdx.x;
    if (e < EE) {
        int dst = ei[EE + e];
        int pos = atomicAdd(&g_cursor[dst], 1);
        g_colidx[et][pos] = ei[e];
    }
}

// ---------------- aggregation: one warp per destination node ------------------
// Batched index loads + lane-parallel exp + shuffle broadcast.
__device__ __forceinline__ float lrelu02(float x) { return x > 0.f ? x : 0.2f * x; }

__global__ void k_agg(int et, const float* __restrict__ bias) {
    int gt = blockIdx.x * blockDim.x + threadIdx.x;
    int w = gt >> 5, lane = gt & 31;
    if (w >= NN) return;

    const float4 ald = *(const float4*)(g_ald + (size_t)w * 4);
    int start = g_rowptr[et][w];
    int end = g_rowptr[et][w + 1];
    int hsel = lane >> 4;

    float4 acc1 = make_float4(0, 0, 0, 0);
    float4 acc2 = make_float4(0, 0, 0, 0);
    float se0 = 0, se1 = 0, se2 = 0, se3 = 0;

    // self loop (exp computed redundantly once; se added on lane 0 only)
    {
        float4 als = *(const float4*)(g_als + (size_t)w * 4);
        float x0 = __expf(lrelu02(als.x + ald.x));
        float x1 = __expf(lrelu02(als.y + ald.y));
        float x2 = __expf(lrelu02(als.z + ald.z));
        float x3 = __expf(lrelu02(als.w + ald.w));
        if (lane == 0) { se0 += x0; se1 += x1; se2 += x2; se3 += x3; }
        float ex1 = hsel ? x1 : x0;
        float ex2 = hsel ? x3 : x2;
        const float4* hp = (const float4*)(g_h + (size_t)w * 256);
        float4 v1 = hp[lane], v2 = hp[32 + lane];
        acc1.x += ex1 * v1.x; acc1.y += ex1 * v1.y;
        acc1.z += ex1 * v1.z; acc1.w += ex1 * v1.w;
        acc2.x += ex2 * v2.x; acc2.y += ex2 * v2.y;
        acc2.z += ex2 * v2.z; acc2.w += ex2 * v2.w;
    }

    for (int base = start; base < end; base += 32) {
        int n = min(32, end - base);
        int mysrc = 0;
        float mx0 = 0.f, mx1 = 0.f, mx2 = 0.f, mx3 = 0.f;
        if (base + lane < end) {
            mysrc = g_colidx[et][base + lane];
            float4 als = *(const float4*)(g_als + (size_t)mysrc * 4);
            mx0 = __expf(lrelu02(als.x + ald.x));
            mx1 = __expf(lrelu02(als.y + ald.y));
            mx2 = __expf(lrelu02(als.z + ald.z));
            mx3 = __expf(lrelu02(als.w + ald.w));
            se0 += mx0; se1 += mx1; se2 += mx2; se3 += mx3;
        }
        for (int j = 0; j < n; j++) {
            int src = __shfl_sync(0xffffffffu, mysrc, j);
            float x0 = __shfl_sync(0xffffffffu, mx0, j);
            float x1 = __shfl_sync(0xffffffffu, mx1, j);
            float x2 = __shfl_sync(0xffffffffu, mx2, j);
            float x3 = __shfl_sync(0xffffffffu, mx3, j);
            float ex1 = hsel ? x1 : x0;
            float ex2 = hsel ? x3 : x2;
            const float4* hp = (const float4*)(g_h + (size_t)src * 256);
            float4 v1 = hp[lane], v2 = hp[32 + lane];
            acc1.x += ex1 * v1.x; acc1.y += ex1 * v1.y;
            acc1.z += ex1 * v1.z; acc1.w += ex1 * v1.w;
            acc2.x += ex2 * v2.x; acc2.y += ex2 * v2.y;
            acc2.z += ex2 * v2.z; acc2.w += ex2 * v2.w;
        }
    }

    // reduce denominators across lanes
#pragma unroll
    for (int off = 16; off; off >>= 1) {
        se0 += __shfl_xor_sync(0xffffffffu, se0, off);
        se1 += __shfl_xor_sync(0xffffffffu, se1, off);
        se2 += __shfl_xor_sync(0xffffffffu, se2, off);
        se3 += __shfl_xor_sync(0xffffffffu, se3, off);
    }

    float inv1 = 1.0f / ((hsel ? se1 : se0) + 1e-16f);
    float inv2 = 1.0f / ((hsel ? se3 : se2) + 1e-16f);
    const float4* bp = (const float4*)bias;
    float4 b1 = bp[lane], b2 = bp[32 + lane];
    float4 o1 = make_float4(acc1.x * inv1 + b1.x, acc1.y * inv1 + b1.y,
                            acc1.z * inv1 + b1.z, acc1.w * inv1 + b1.w);
    float4 o2 = make_float4(acc2.x * inv2 + b2.x, acc2.y * inv2 + b2.y,
                            acc2.z * inv2 + b2.z, acc2.w * inv2 + b2.w);
    *(float4*)(g_out + (size_t)w * 256 + lane * 4) = o1;
    *(float4*)(g_out + (size_t)w * 256 + 128 + lane * 4) = o2;
}

// ---------------- batchnorm ---------------------------------------------------
__global__ void k_bnstat() {
    int col = threadIdx.x;
    int b = blockIdx.x;
    int n0 = b * 250;
    float s = 0.f, s2 = 0.f;
    for (int n = n0; n < n0 + 250; n++) {
        float v = g_out[(size_t)n * 256 + col];
        s += v;
        s2 += v * v;
    }
    atomicAdd(&g_bnstat[col], s);
    atomicAdd(&g_bnstat[256 + col], s2);
}

// BN + ReLU + bf16 hi/lo split for the next layer's A operand
__global__ void k_bnsplit(const float* __restrict__ gam, const float* __restrict__ bet) {
    int i = blockIdx.x * blockDim.x + threadIdx.x;
    if (i >= NN * 64) return;
    int colb = (i & 63) * 4;
    float4 v = ((const float4*)g_out)[i];
    float invN = 1.0f / (float)NN;
    float out[4];
    float vv[4] = {v.x, v.y, v.z, v.w};
#pragma unroll
    for (int c = 0; c < 4; c++) {
        float mu = g_bnstat[colb + c] * invN;
        float var = g_bnstat[256 + colb + c] * invN - mu * mu;
        float sc = gam[colb + c] * rsqrtf(var + EPSBN);
        float y = (vv[c] - mu) * sc + bet[colb + c];
        out[c] = y > 0.f ? y : 0.f;
    }
    uint32_t h01, l01, h23, l23;
    split2(out[0], out[1], h01, l01);
    split2(out[2], out[3], h23, l23);
    *(uint2*)(g_a_hi + (size_t)i * 4) = make_uint2(h01, h23);
    *(uint2*)(g_a_lo + (size_t)i * 4) = make_uint2(l01, l23);
}

// ---------------- final linear 256 -> 32 --------------------------------------
__global__ void k_lin(const float* __restrict__ Wl, const float* __restrict__ bl,
                      float* __restrict__ out) {
    int gt = blockIdx.x * blockDim.x + threadIdx.x;
    int w = gt >> 5, lane = gt & 31;
    if (w >= NN) return;
    float acc = bl[lane];
    const __nv_bfloat16* ah = g_a_hi + (size_t)w * 256;
    const __nv_bfloat16* al = g_a_lo + (size_t)w * 256;
    for (int kb = 0; kb < 256; kb += 32) {
        float av = __bfloat162float(ah[kb + lane]) + __bfloat162float(al[kb + lane]);
#pragma unroll
        for (int kk = 0; kk < 32; kk++) {
            float a = __shfl_sync(0xffffffffu, av, kk);
            acc += a * Wl[(kb + kk) * 32 + lane];
        }
    }
    out[(size_t)w * 32 + lane] = acc;
}

// ---------------- launch ------------------------------------------------------
extern "C" void kernel_launch(void* const* d_in, const int* in_sizes, int n_in,
                              void* d_out, int out_size) {
    (void)in_sizes; (void)n_in; (void)out_size;
    const float* x = (const float*)d_in[0];
    const int* eis = (const int*)d_in[1];
    const int* eit = (const int*)d_in[2];
    const float* W[4]  = {(const float*)d_in[3],  (const float*)d_in[9],
                          (const float*)d_in[15], (const float*)d_in[21]};
    const float* AS[4] = {(const float*)d_in[4],  (const float*)d_in[10],
                          (const float*)d_in[16], (const float*)d_in[22]};
    const float* AD[4] = {(const float*)d_in[5],  (const float*)d_in[11],
                          (const float*)d_in[17], (const float*)d_in[23]};
    const float* BI[4] = {(const float*)d_in[6],  (const float*)d_in[12],
                          (const float*)d_in[18], (const float*)d_in[24]};
    const float* GA[4] = {(const float*)d_in[7],  (const float*)d_in[13],
                          (const float*)d_in[19], (const float*)d_in[25]};
    const float* BE[4] = {(const float*)d_in[8],  (const float*)d_in[14],
                          (const float*)d_in[20], (const float*)d_in[26]};
    const float* Wl = (const float*)d_in[27];
    const float* bl = (const float*)d_in[28];

    cudaFuncSetAttribute(k_gemm2, cudaFuncAttributeMaxDynamicSharedMemorySize, SMEM_GEMM);

    const int scanBlocks = (NN + 1023) / 1024;
    dim3 ggemm(NTILES, 2);

    k_wprep<<<dim3(256, 4), 256>>>(W[0], W[1], W[2], W[3]);
    k_xprep<<<(NN * 32 + 255) / 256, 256>>>(x);

    // CSR build for both edge types; layer-1 GEMM interleaved
    k_zero_deg<<<(NN + 255) / 256, 256>>>();
    k_hist<<<(EE + 255) / 256, 256>>>(eis);
    k_gemm2<<<ggemm, 256, SMEM_GEMM>>>(128, 0);
    k_scan1<<<scanBlocks, 1024>>>(0);
    k_scan2<<<1, 32>>>(scanBlocks);
    k_scan3<<<scanBlocks, 1024>>>(0);
    k_cursor<<<(NN + 255) / 256, 256>>>(0);
    k_scatter<<<(EE + 255) / 256, 256>>>(eis, 0);

    k_zero_deg<<<(NN + 255) / 256, 256>>>();
    k_hist<<<(EE + 255) / 256, 256>>>(eit);
    k_scan1<<<scanBlocks, 1024>>>(1);
    k_scan2<<<1, 32>>>(scanBlocks);
    k_scan3<<<scanBlocks, 1024>>>(1);
    k_cursor<<<(NN + 255) / 256, 256>>>(1);
    k_scatter<<<(EE + 255) / 256, 256>>>(eit, 1);

    int ET[4] = {0, 0, 1, 1};
    for (int l = 0; l < 4; l++) {
        if (l > 0) k_gemm2<<<ggemm, 256, SMEM_GEMM>>>(256, l);
        k_al<<<(NN * 32 + 255) / 256, 256>>>(AS[l], AD[l]);
        k_agg<<<(NN * 32 + 255) / 256, 256>>>(ET[l], BI[l]);
        k_zero_bn<<<2, 256>>>();
        k_bnstat<<<200, 256>>>();
        k_bnsplit<<<(NN * 64 + 255) / 256, 256>>>(GA[l], BE[l]);
    }
    k_lin<<<(NN * 32 + 255) / 256, 256>>>(Wl, bl, (float*)d_out);
}